// round 12
// baseline (speedup 1.0000x reference)
#include <cuda_runtime.h>
#include <cuda_bf16.h>

#define NE 8
#define TT 8192
#define HH 1024
#define II 4096

typedef unsigned int u32;

// ---- separate hi/lo bf16 planes ----
__device__ __nv_bfloat16 g_xh[(size_t)TT * HH],  g_xl[(size_t)TT * HH];
__device__ __nv_bfloat16 g_w1h[(size_t)NE * HH * II], g_w1l[(size_t)NE * HH * II];
__device__ __nv_bfloat16 g_w2h[(size_t)NE * II * HH], g_w2l[(size_t)NE * II * HH];
__device__ __nv_bfloat16 g_uph[(size_t)TT * II], g_upl[(size_t)TT * II];

// ---- smem stage (halves): Ahi/Alo [128][40], Bhi/Blo [32][72], BK = 32 ----
#define A_ROW 40
#define B_ROW 72
#define OFF_ALO (128 * A_ROW)                  // 5120
#define OFF_BHI (2 * 128 * A_ROW)              // 10240
#define OFF_BLO (OFF_BHI + 32 * B_ROW)         // 12544
#define STAGE_H (OFF_BHI + 2 * 32 * B_ROW)     // 14848 halves
#define STAGE_B (STAGE_H * 2)                  // 29696 bytes
#define NSTAGE  3
#define SMEM_BYTES (NSTAGE * STAGE_B)          // 89088 (x2 CTAs = 178KB/SM)

static __device__ __forceinline__ u32 smem_u32(const void* p) {
    u32 a;
    asm("{ .reg .u64 t; cvta.to.shared.u64 t, %1; cvt.u32.u64 %0, t; }" : "=r"(a) : "l"(p));
    return a;
}

#define CP16(dst, src) \
    asm volatile("cp.async.cg.shared.global [%0], [%1], 16;" :: "r"(dst), "l"(src))
#define CP_COMMIT() asm volatile("cp.async.commit_group;" ::: "memory")
#define CP_WAIT1()  asm volatile("cp.async.wait_group 1;" ::: "memory")

#define LDSM4(r, addr)                                                        \
    asm volatile("ldmatrix.sync.aligned.m8n8.x4.shared.b16 {%0,%1,%2,%3}, [%4];" \
                 : "=r"((r)[0]), "=r"((r)[1]), "=r"((r)[2]), "=r"((r)[3])     \
                 : "r"(addr))

#define LDSM4T(r, addr)                                                       \
    asm volatile("ldmatrix.sync.aligned.m8n8.x4.trans.shared.b16 {%0,%1,%2,%3}, [%4];" \
                 : "=r"((r)[0]), "=r"((r)[1]), "=r"((r)[2]), "=r"((r)[3])     \
                 : "r"(addr))

#define MMA16816(d, a, b0, b1)                                                \
    asm volatile("mma.sync.aligned.m16n8k16.row.col.f32.bf16.bf16.f32 "       \
                 "{%0,%1,%2,%3},{%4,%5,%6,%7},{%8,%9},{%0,%1,%2,%3};"         \
                 : "+f"((d)[0]), "+f"((d)[1]), "+f"((d)[2]), "+f"((d)[3])     \
                 : "r"((a)[0]), "r"((a)[1]), "r"((a)[2]), "r"((a)[3]),        \
                   "r"(b0), "r"(b1))

static __device__ __forceinline__ void cvt_hilo(float x, float y, u32& h, u32& l) {
    __nv_bfloat162 hb = __float22bfloat162_rn(make_float2(x, y));
    float2 hf = __bfloat1622float2(hb);
    __nv_bfloat162 lb = __float22bfloat162_rn(make_float2(x - hf.x, y - hf.y));
    h = *(u32*)&hb;
    l = *(u32*)&lb;
}

__global__ __launch_bounds__(256)
void cvt_split_k(const float4* __restrict__ src, uint2* __restrict__ h,
                 uint2* __restrict__ l, int n4)
{
    int i = blockIdx.x * 256 + threadIdx.x;
    if (i < n4) {
        float4 v = src[i];
        u32 h0, l0, h1, l1;
        cvt_hilo(v.x, v.y, h0, l0);
        cvt_hilo(v.z, v.w, h1, l1);
        h[i] = make_uint2(h0, h1);
        l[i] = make_uint2(l0, l1);
    }
}

// C[row0:+128, n0:+64] = A[rows,:K] @ W[e,:K,n0:+64]; plane operands.
// 128 threads, warp tile 64x32, fully double-buffered register fragments.
template <int K, int N, int EPI>
__global__ __launch_bounds__(128, 2)
void gemm_moe(const __nv_bfloat16* __restrict__ Ah, const __nv_bfloat16* __restrict__ Al,
              const __nv_bfloat16* __restrict__ Wh, const __nv_bfloat16* __restrict__ Wl,
              const int* __restrict__ bsz, float* __restrict__ C,
              __nv_bfloat16* __restrict__ Ch, __nv_bfloat16* __restrict__ Cl)
{
    extern __shared__ __nv_bfloat16 sm[];
    const u32 sbase = smem_u32(sm);
    const int tid = threadIdx.x;
    const int lane = tid & 31;
    const int wid = tid >> 5;
    const int warp_m = wid & 1;    // 2 warps along m (64 rows each)
    const int warp_n = wid >> 1;   // 2 warps along n (32 cols each)
    const int row0 = blockIdx.y * 128;
    const int n0 = blockIdx.x * 64;

    int cum = 0, e = 0;
#pragma unroll
    for (int i = 0; i < NE; i++) { if (row0 >= cum) e = i; cum += bsz[i]; }
    const size_t woff = (size_t)e * (size_t)K * (size_t)N;

    // ---- cp.async mapping (128 threads) ----
    const int ar = tid >> 2, ac = tid & 3;   // A: rows ar+{0,32,64,96}, chunk ac of 4
    const int bk = tid >> 3, bc = tid & 7;   // B: rows bk, bk+16, chunk bc of 8
    const __nv_bfloat16* pAh = Ah + (size_t)(row0 + ar) * K + ac * 8;
    const __nv_bfloat16* pAl = Al + (size_t)(row0 + ar) * K + ac * 8;
    const __nv_bfloat16* pBh = Wh + woff + (size_t)bk * N + n0 + bc * 8;
    const __nv_bfloat16* pBl = Wl + woff + (size_t)bk * N + n0 + bc * 8;
    const u32 dA = sbase + (u32)((ar * A_ROW + ac * 8) * 2);
    const u32 dB = sbase + (u32)(OFF_BHI * 2 + (bk * B_ROW + bc * 8) * 2);

    // ---- ldmatrix lane bases ----
    const int a_r = lane & 15, a_c = (lane >> 4) * 8;
    const u32 aoff = sbase + (u32)(((warp_m * 64 + a_r) * A_ROW + a_c) * 2);
    const int b_k = (lane & 7) + 8 * ((lane >> 3) & 1);
    const int b_n = 8 * (lane >> 4);
    const u32 boff = sbase + (u32)((OFF_BHI + b_k * B_ROW + warp_n * 32 + b_n) * 2);

    float acc[4][4][4];
#pragma unroll
    for (int mf = 0; mf < 4; mf++)
#pragma unroll
        for (int nf = 0; nf < 4; nf++)
#pragma unroll
            for (int v = 0; v < 4; v++) acc[mf][nf][v] = 0.0f;

    // double-buffered fragments
    u32 fAh[2][16], fAl[2][16], fBh[2][8], fBl[2][8];

    const int NS = K >> 5;

#define LOAD_STAGE(stoff)                                                     \
    do {                                                                      \
        const u32 _a = dA + (stoff);                                          \
        const u32 _b = dB + (stoff);                                          \
        CP16(_a,                       pAh);                                  \
        CP16(_a + 32 * A_ROW * 2,      pAh + (size_t)32 * K);                 \
        CP16(_a + 64 * A_ROW * 2,      pAh + (size_t)64 * K);                 \
        CP16(_a + 96 * A_ROW * 2,      pAh + (size_t)96 * K);                 \
        CP16(_a + OFF_ALO * 2,                     pAl);                      \
        CP16(_a + OFF_ALO * 2 + 32 * A_ROW * 2,    pAl + (size_t)32 * K);     \
        CP16(_a + OFF_ALO * 2 + 64 * A_ROW * 2,    pAl + (size_t)64 * K);     \
        CP16(_a + OFF_ALO * 2 + 96 * A_ROW * 2,    pAl + (size_t)96 * K);     \
        CP16(_b,                       pBh);                                  \
        CP16(_b + 16 * B_ROW * 2,      pBh + (size_t)16 * N);                 \
        CP16(_b + (OFF_BLO - OFF_BHI) * 2,                  pBl);             \
        CP16(_b + (OFF_BLO - OFF_BHI) * 2 + 16 * B_ROW * 2, pBl + (size_t)16 * N); \
        pAh += 32; pAl += 32;                                                 \
        pBh += (size_t)32 * N; pBl += (size_t)32 * N;                         \
    } while (0)

    // frags for half-stage ki (k offset ki*16) of stage at byte offset stoff -> buffer b
#define LDSM_FRAGS(b, stoff, ki)                                              \
    do {                                                                      \
        const u32 _ka = aoff + (stoff) + (ki) * 32;                           \
        const u32 _kb = boff + (stoff) + (ki) * (16 * B_ROW * 2);             \
        LDSM4(&fAh[b][0],  _ka);                                              \
        LDSM4(&fAh[b][4],  _ka + 16 * A_ROW * 2);                             \
        LDSM4(&fAh[b][8],  _ka + 32 * A_ROW * 2);                             \
        LDSM4(&fAh[b][12], _ka + 48 * A_ROW * 2);                             \
        LDSM4(&fAl[b][0],  _ka + OFF_ALO * 2);                                \
        LDSM4(&fAl[b][4],  _ka + OFF_ALO * 2 + 16 * A_ROW * 2);               \
        LDSM4(&fAl[b][8],  _ka + OFF_ALO * 2 + 32 * A_ROW * 2);               \
        LDSM4(&fAl[b][12], _ka + OFF_ALO * 2 + 48 * A_ROW * 2);               \
        LDSM4T(&fBh[b][0], _kb);                                              \
        LDSM4T(&fBh[b][4], _kb + 16 * 2);                                     \
        LDSM4T(&fBl[b][0], _kb + (OFF_BLO - OFF_BHI) * 2);                    \
        LDSM4T(&fBl[b][4], _kb + (OFF_BLO - OFF_BHI) * 2 + 16 * 2);           \
    } while (0)

#define BURST(fa, fb, b)                                                      \
    do {                                                                      \
        _Pragma("unroll")                                                     \
        for (int mf = 0; mf < 4; mf++)                                        \
            _Pragma("unroll")                                                 \
            for (int nf = 0; nf < 4; nf++)                                    \
                MMA16816(acc[mf][nf], &fa[b][mf * 4], fb[b][nf * 2],          \
                         fb[b][nf * 2 + 1]);                                  \
    } while (0)

    LOAD_STAGE(0);         CP_COMMIT();
    LOAD_STAGE(STAGE_B);   CP_COMMIT();

    int sidx = 0;
    for (int s = 0; s < NS; s++) {
        CP_WAIT1();
        __syncthreads();

        if (s + 2 < NS) {
            int pidx = sidx + 2; if (pidx >= 3) pidx -= 3;
            LOAD_STAGE((u32)(pidx * STAGE_B));
        }
        CP_COMMIT();

        const u32 stb = (u32)(sidx * STAGE_B);
        sidx++; if (sidx >= 3) sidx -= 3;

        LDSM_FRAGS(0, stb, 0);          // ki=0 frags -> buf0
        BURST(fAh, fBh, 0);             // AhBh (ki0)
        LDSM_FRAGS(1, stb, 1);          // ki=1 frags -> buf1 (no WAR: distinct regs)
        BURST(fAh, fBl, 0);             // AhBl (ki0)
        BURST(fAl, fBh, 0);             // AlBh (ki0)
        BURST(fAh, fBh, 1);             // AhBh (ki1)
        BURST(fAh, fBl, 1);             // AhBl (ki1)
        BURST(fAl, fBh, 1);             // AlBh (ki1)
    }
#undef LOAD_STAGE
#undef LDSM_FRAGS
#undef BURST

    // ---- epilogue ----
#pragma unroll
    for (int mf = 0; mf < 4; mf++)
#pragma unroll
        for (int nf = 0; nf < 4; nf++) {
            int r = row0 + warp_m * 64 + mf * 16 + (lane >> 2);
            int c = n0 + warp_n * 32 + nf * 8 + (lane & 3) * 2;
            if (EPI == 0) {
                *(float2*)(C + (size_t)r * N + c) =
                    make_float2(acc[mf][nf][0], acc[mf][nf][1]);
                *(float2*)(C + (size_t)(r + 8) * N + c) =
                    make_float2(acc[mf][nf][2], acc[mf][nf][3]);
            } else {
                u32 h, l;
                cvt_hilo(acc[mf][nf][0], acc[mf][nf][1], h, l);
                *(u32*)(Ch + (size_t)r * N + c) = h;
                *(u32*)(Cl + (size_t)r * N + c) = l;
                cvt_hilo(acc[mf][nf][2], acc[mf][nf][3], h, l);
                *(u32*)(Ch + (size_t)(r + 8) * N + c) = h;
                *(u32*)(Cl + (size_t)(r + 8) * N + c) = l;
            }
        }
}

extern "C" void kernel_launch(void* const* d_in, const int* in_sizes, int n_in,
                              void* d_out, int out_size)
{
    const float* hiddens = (const float*)d_in[0];
    const int*   bsz     = (const int*)d_in[1];
    const float* w1      = (const float*)d_in[2];
    const float* w2      = (const float*)d_in[3];
    float*       out     = (float*)d_out;

    __nv_bfloat16 *xh, *xl, *w1h, *w1l, *w2h, *w2l, *uph, *upl;
    cudaGetSymbolAddress((void**)&xh, g_xh);   cudaGetSymbolAddress((void**)&xl, g_xl);
    cudaGetSymbolAddress((void**)&w1h, g_w1h); cudaGetSymbolAddress((void**)&w1l, g_w1l);
    cudaGetSymbolAddress((void**)&w2h, g_w2h); cudaGetSymbolAddress((void**)&w2l, g_w2l);
    cudaGetSymbolAddress((void**)&uph, g_uph); cudaGetSymbolAddress((void**)&upl, g_upl);

    cudaFuncSetAttribute(gemm_moe<1024, 4096, 1>, cudaFuncAttributeMaxDynamicSharedMemorySize, SMEM_BYTES);
    cudaFuncSetAttribute(gemm_moe<4096, 1024, 0>, cudaFuncAttributeMaxDynamicSharedMemorySize, SMEM_BYTES);

    {
        int n4 = (TT * HH) / 4;
        cvt_split_k<<<(n4 + 255) / 256, 256>>>((const float4*)hiddens, (uint2*)xh, (uint2*)xl, n4);
    }
    {
        int n4 = (NE * HH * II) / 4;
        cvt_split_k<<<(n4 + 255) / 256, 256>>>((const float4*)w1, (uint2*)w1h, (uint2*)w1l, n4);
        cvt_split_k<<<(n4 + 255) / 256, 256>>>((const float4*)w2, (uint2*)w2h, (uint2*)w2l, n4);
    }

    // up = hiddens @ w1[e] : K=1024, N=4096 ; hi/lo plane output
    gemm_moe<1024, 4096, 1><<<dim3(II / 64, TT / 128), 128, SMEM_BYTES>>>(
        xh, xl, w1h, w1l, bsz, nullptr, uph, upl);
    // down = up @ w2[e] : K=4096, N=1024 ; fp32 output
    gemm_moe<4096, 1024, 0><<<dim3(HH / 64, TT / 128), 128, SMEM_BYTES>>>(
        uph, upl, w2h, w2l, bsz, out, nullptr, nullptr);
}

// round 13
// speedup vs baseline: 1.5051x; 1.5051x over previous
#include <cuda_runtime.h>
#include <cuda_fp16.h>

#define NE 8
#define TT 8192
#define HH 1024
#define II 4096

typedef unsigned int u32;

// ---- fp16 planes: A-side split hi/lo, B-side hi only ----
__device__ __half g_xh[(size_t)TT * HH],  g_xl[(size_t)TT * HH];
__device__ __half g_w1h[(size_t)NE * HH * II];
__device__ __half g_w2h[(size_t)NE * II * HH];
__device__ __half g_uph[(size_t)TT * II], g_upl[(size_t)TT * II];

// ---- smem stage (halves): Ah/Al [128][40], Bh [32][72], BK = 32 ----
#define A_ROW 40
#define B_ROW 72
#define OFF_ALO (128 * A_ROW)                  // 5120
#define OFF_BH  (2 * 128 * A_ROW)              // 10240
#define STAGE_H (OFF_BH + 32 * B_ROW)          // 12544 halves
#define STAGE_B (STAGE_H * 2)                  // 25088 bytes
#define NSTAGE  3
#define SMEM_BYTES (NSTAGE * STAGE_B)          // 75264 (x2 CTAs = 147KB/SM)

static __device__ __forceinline__ u32 smem_u32(const void* p) {
    u32 a;
    asm("{ .reg .u64 t; cvta.to.shared.u64 t, %1; cvt.u32.u64 %0, t; }" : "=r"(a) : "l"(p));
    return a;
}

#define CP16(dst, src) \
    asm volatile("cp.async.cg.shared.global [%0], [%1], 16;" :: "r"(dst), "l"(src))
#define CP_COMMIT() asm volatile("cp.async.commit_group;" ::: "memory")
#define CP_WAIT1()  asm volatile("cp.async.wait_group 1;" ::: "memory")

#define LDSM4(r, addr)                                                        \
    asm volatile("ldmatrix.sync.aligned.m8n8.x4.shared.b16 {%0,%1,%2,%3}, [%4];" \
                 : "=r"((r)[0]), "=r"((r)[1]), "=r"((r)[2]), "=r"((r)[3])     \
                 : "r"(addr))

#define LDSM4T(r, addr)                                                       \
    asm volatile("ldmatrix.sync.aligned.m8n8.x4.trans.shared.b16 {%0,%1,%2,%3}, [%4];" \
                 : "=r"((r)[0]), "=r"((r)[1]), "=r"((r)[2]), "=r"((r)[3])     \
                 : "r"(addr))

#define MMA16816(d, a, b0, b1)                                                \
    asm volatile("mma.sync.aligned.m16n8k16.row.col.f32.f16.f16.f32 "         \
                 "{%0,%1,%2,%3},{%4,%5,%6,%7},{%8,%9},{%0,%1,%2,%3};"         \
                 : "+f"((d)[0]), "+f"((d)[1]), "+f"((d)[2]), "+f"((d)[3])     \
                 : "r"((a)[0]), "r"((a)[1]), "r"((a)[2]), "r"((a)[3]),        \
                   "r"(b0), "r"(b1))

// fp16 split: h = rn(x), l = rn(x - h); packs pairs into u32
static __device__ __forceinline__ void cvt_hilo(float x, float y, u32& h, u32& l) {
    __half2 hb = __float22half2_rn(make_float2(x, y));
    float2 hf = __half22float2(hb);
    __half2 lb = __float22half2_rn(make_float2(x - hf.x, y - hf.y));
    h = *(u32*)&hb;
    l = *(u32*)&lb;
}

// full split (A-side operands)
__global__ __launch_bounds__(256)
void cvt_split_k(const float4* __restrict__ src, uint2* __restrict__ h,
                 uint2* __restrict__ l, int n4)
{
    int i = blockIdx.x * 256 + threadIdx.x;
    if (i < n4) {
        float4 v = src[i];
        u32 h0, l0, h1, l1;
        cvt_hilo(v.x, v.y, h0, l0);
        cvt_hilo(v.z, v.w, h1, l1);
        h[i] = make_uint2(h0, h1);
        l[i] = make_uint2(l0, l1);
    }
}

// hi-only truncation (B-side weights)
__global__ __launch_bounds__(256)
void cvt_hi_k(const float4* __restrict__ src, uint2* __restrict__ h, int n4)
{
    int i = blockIdx.x * 256 + threadIdx.x;
    if (i < n4) {
        float4 v = src[i];
        __half2 h0 = __float22half2_rn(make_float2(v.x, v.y));
        __half2 h1 = __float22half2_rn(make_float2(v.z, v.w));
        h[i] = make_uint2(*(u32*)&h0, *(u32*)&h1);
    }
}

// C[row0:+128, n0:+64] = A[rows,:K] @ W[e,:K,n0:+64]
// A: fp16 hi/lo planes; W: fp16 hi plane. 2 MMA products: AhBh + AlBh.
// EPI=0: fp32 C.  EPI=1: fp16 hi/lo planes Ch/Cl.
template <int K, int N, int EPI>
__global__ __launch_bounds__(128, 2)
void gemm_moe(const __half* __restrict__ Ah, const __half* __restrict__ Al,
              const __half* __restrict__ Wh,
              const int* __restrict__ bsz, float* __restrict__ C,
              __half* __restrict__ Ch, __half* __restrict__ Cl)
{
    extern __shared__ __half sm[];
    const u32 sbase = smem_u32(sm);
    const int tid = threadIdx.x;
    const int lane = tid & 31;
    const int wid = tid >> 5;
    const int warp_m = wid & 1;    // 2 warps along m (64 rows each)
    const int warp_n = wid >> 1;   // 2 warps along n (32 cols each)
    const int row0 = blockIdx.y * 128;
    const int n0 = blockIdx.x * 64;

    int cum = 0, e = 0;
#pragma unroll
    for (int i = 0; i < NE; i++) { if (row0 >= cum) e = i; cum += bsz[i]; }
    const size_t woff = (size_t)e * (size_t)K * (size_t)N;

    // ---- cp.async mapping (128 threads) ----
    const int ar = tid >> 2, ac = tid & 3;   // A: rows ar+{0,32,64,96}, chunk ac of 4
    const int bk = tid >> 3, bc = tid & 7;   // B: rows bk, bk+16, chunk bc of 8
    const __half* pAh = Ah + (size_t)(row0 + ar) * K + ac * 8;
    const __half* pAl = Al + (size_t)(row0 + ar) * K + ac * 8;
    const __half* pBh = Wh + woff + (size_t)bk * N + n0 + bc * 8;
    const u32 dA = sbase + (u32)((ar * A_ROW + ac * 8) * 2);
    const u32 dB = sbase + (u32)(OFF_BH * 2 + (bk * B_ROW + bc * 8) * 2);

    // ---- ldmatrix lane bases ----
    const int a_r = lane & 15, a_c = (lane >> 4) * 8;
    const u32 aoff = sbase + (u32)(((warp_m * 64 + a_r) * A_ROW + a_c) * 2);
    const int b_k = (lane & 7) + 8 * ((lane >> 3) & 1);
    const int b_n = 8 * (lane >> 4);
    const u32 boff = sbase + (u32)((OFF_BH + b_k * B_ROW + warp_n * 32 + b_n) * 2);

    float acc[4][4][4];
#pragma unroll
    for (int mf = 0; mf < 4; mf++)
#pragma unroll
        for (int nf = 0; nf < 4; nf++)
#pragma unroll
            for (int v = 0; v < 4; v++) acc[mf][nf][v] = 0.0f;

    // double-buffered fragments (per half-stage ki)
    u32 fAh[2][16], fAl[2][16], fB[2][8];

    const int NS = K >> 5;

#define LOAD_STAGE(stoff)                                                     \
    do {                                                                      \
        const u32 _a = dA + (stoff);                                          \
        const u32 _b = dB + (stoff);                                          \
        CP16(_a,                       pAh);                                  \
        CP16(_a + 32 * A_ROW * 2,      pAh + (size_t)32 * K);                 \
        CP16(_a + 64 * A_ROW * 2,      pAh + (size_t)64 * K);                 \
        CP16(_a + 96 * A_ROW * 2,      pAh + (size_t)96 * K);                 \
        CP16(_a + OFF_ALO * 2,                     pAl);                      \
        CP16(_a + OFF_ALO * 2 + 32 * A_ROW * 2,    pAl + (size_t)32 * K);     \
        CP16(_a + OFF_ALO * 2 + 64 * A_ROW * 2,    pAl + (size_t)64 * K);     \
        CP16(_a + OFF_ALO * 2 + 96 * A_ROW * 2,    pAl + (size_t)96 * K);     \
        CP16(_b,                       pBh);                                  \
        CP16(_b + 16 * B_ROW * 2,      pBh + (size_t)16 * N);                 \
        pAh += 32; pAl += 32;                                                 \
        pBh += (size_t)32 * N;                                                \
    } while (0)

#define LDSM_FRAGS(b, stoff, ki)                                              \
    do {                                                                      \
        const u32 _ka = aoff + (stoff) + (ki) * 32;                           \
        const u32 _kb = boff + (stoff) + (ki) * (16 * B_ROW * 2);             \
        LDSM4(&fAh[b][0],  _ka);                                              \
        LDSM4(&fAh[b][4],  _ka + 16 * A_ROW * 2);                             \
        LDSM4(&fAh[b][8],  _ka + 32 * A_ROW * 2);                             \
        LDSM4(&fAh[b][12], _ka + 48 * A_ROW * 2);                             \
        LDSM4(&fAl[b][0],  _ka + OFF_ALO * 2);                                \
        LDSM4(&fAl[b][4],  _ka + OFF_ALO * 2 + 16 * A_ROW * 2);               \
        LDSM4(&fAl[b][8],  _ka + OFF_ALO * 2 + 32 * A_ROW * 2);               \
        LDSM4(&fAl[b][12], _ka + OFF_ALO * 2 + 48 * A_ROW * 2);               \
        LDSM4T(&fB[b][0],  _kb);                                              \
        LDSM4T(&fB[b][4],  _kb + 16 * 2);                                     \
    } while (0)

#define BURST(fa, b)                                                          \
    do {                                                                      \
        _Pragma("unroll")                                                     \
        for (int mf = 0; mf < 4; mf++)                                        \
            _Pragma("unroll")                                                 \
            for (int nf = 0; nf < 4; nf++)                                    \
                MMA16816(acc[mf][nf], &fa[b][mf * 4], fB[b][nf * 2],          \
                         fB[b][nf * 2 + 1]);                                  \
    } while (0)

    LOAD_STAGE(0);         CP_COMMIT();
    LOAD_STAGE(STAGE_B);   CP_COMMIT();

    int sidx = 0;
    for (int s = 0; s < NS; s++) {
        CP_WAIT1();
        __syncthreads();

        if (s + 2 < NS) {
            int pidx = sidx + 2; if (pidx >= 3) pidx -= 3;
            LOAD_STAGE((u32)(pidx * STAGE_B));
        }
        CP_COMMIT();

        const u32 stb = (u32)(sidx * STAGE_B);
        sidx++; if (sidx >= 3) sidx -= 3;

        LDSM_FRAGS(0, stb, 0);          // ki=0 -> buf0
        BURST(fAh, 0);                  // AhBh (ki0)
        LDSM_FRAGS(1, stb, 1);          // ki=1 -> buf1
        BURST(fAl, 0);                  // AlBh (ki0)
        BURST(fAh, 1);                  // AhBh (ki1)
        BURST(fAl, 1);                  // AlBh (ki1)
    }
#undef LOAD_STAGE
#undef LDSM_FRAGS
#undef BURST

    // ---- epilogue ----
#pragma unroll
    for (int mf = 0; mf < 4; mf++)
#pragma unroll
        for (int nf = 0; nf < 4; nf++) {
            int r = row0 + warp_m * 64 + mf * 16 + (lane >> 2);
            int c = n0 + warp_n * 32 + nf * 8 + (lane & 3) * 2;
            if (EPI == 0) {
                *(float2*)(C + (size_t)r * N + c) =
                    make_float2(acc[mf][nf][0], acc[mf][nf][1]);
                *(float2*)(C + (size_t)(r + 8) * N + c) =
                    make_float2(acc[mf][nf][2], acc[mf][nf][3]);
            } else {
                u32 h, l;
                cvt_hilo(acc[mf][nf][0], acc[mf][nf][1], h, l);
                *(u32*)(Ch + (size_t)r * N + c) = h;
                *(u32*)(Cl + (size_t)r * N + c) = l;
                cvt_hilo(acc[mf][nf][2], acc[mf][nf][3], h, l);
                *(u32*)(Ch + (size_t)(r + 8) * N + c) = h;
                *(u32*)(Cl + (size_t)(r + 8) * N + c) = l;
            }
        }
}

extern "C" void kernel_launch(void* const* d_in, const int* in_sizes, int n_in,
                              void* d_out, int out_size)
{
    const float* hiddens = (const float*)d_in[0];
    const int*   bsz     = (const int*)d_in[1];
    const float* w1      = (const float*)d_in[2];
    const float* w2      = (const float*)d_in[3];
    float*       out     = (float*)d_out;

    __half *xh, *xl, *w1h, *w2h, *uph, *upl;
    cudaGetSymbolAddress((void**)&xh, g_xh);   cudaGetSymbolAddress((void**)&xl, g_xl);
    cudaGetSymbolAddress((void**)&w1h, g_w1h); cudaGetSymbolAddress((void**)&w2h, g_w2h);
    cudaGetSymbolAddress((void**)&uph, g_uph); cudaGetSymbolAddress((void**)&upl, g_upl);

    cudaFuncSetAttribute(gemm_moe<1024, 4096, 1>, cudaFuncAttributeMaxDynamicSharedMemorySize, SMEM_BYTES);
    cudaFuncSetAttribute(gemm_moe<4096, 1024, 0>, cudaFuncAttributeMaxDynamicSharedMemorySize, SMEM_BYTES);

    {
        int n4 = (TT * HH) / 4;
        cvt_split_k<<<(n4 + 255) / 256, 256>>>((const float4*)hiddens, (uint2*)xh, (uint2*)xl, n4);
    }
    {
        int n4 = (NE * HH * II) / 4;
        cvt_hi_k<<<(n4 + 255) / 256, 256>>>((const float4*)w1, (uint2*)w1h, n4);
        cvt_hi_k<<<(n4 + 255) / 256, 256>>>((const float4*)w2, (uint2*)w2h, n4);
    }

    // up = hiddens @ w1[e] : K=1024, N=4096 ; fp16 hi/lo plane output
    gemm_moe<1024, 4096, 1><<<dim3(II / 64, TT / 128), 128, SMEM_BYTES>>>(
        xh, xl, w1h, bsz, nullptr, uph, upl);
    // down = up @ w2[e] : K=4096, N=1024 ; fp32 output
    gemm_moe<4096, 1024, 0><<<dim3(HH / 64, TT / 128), 128, SMEM_BYTES>>>(
        uph, upl, w2h, bsz, out, nullptr, nullptr);
}

// round 14
// speedup vs baseline: 2.5611x; 1.7015x over previous
#include <cuda_runtime.h>
#include <cuda_fp16.h>

#define NE 8
#define TT 8192
#define HH 1024
#define II 4096

typedef unsigned int u32;

// ---- pure fp16 operand planes ----
__device__ __half g_xh[(size_t)TT * HH];
__device__ __half g_w1h[(size_t)NE * HH * II];
__device__ __half g_w2h[(size_t)NE * II * HH];
__device__ __half g_uph[(size_t)TT * II];

// ---- smem stage (halves): A [128][40], B [32][72], BK = 32 ----
#define A_ROW 40
#define B_ROW 72
#define OFF_BH  (128 * A_ROW)                  // 5120
#define STAGE_H (OFF_BH + 32 * B_ROW)          // 7424 halves
#define STAGE_B (STAGE_H * 2)                  // 14848 bytes
#define NSTAGE  3
#define SMEM_BYTES (NSTAGE * STAGE_B)          // 44544 (x3 CTAs = 133KB/SM)

static __device__ __forceinline__ u32 smem_u32(const void* p) {
    u32 a;
    asm("{ .reg .u64 t; cvta.to.shared.u64 t, %1; cvt.u32.u64 %0, t; }" : "=r"(a) : "l"(p));
    return a;
}

#define CP16(dst, src) \
    asm volatile("cp.async.cg.shared.global [%0], [%1], 16;" :: "r"(dst), "l"(src))
#define CP_COMMIT() asm volatile("cp.async.commit_group;" ::: "memory")
#define CP_WAIT1()  asm volatile("cp.async.wait_group 1;" ::: "memory")

#define LDSM4(r, addr)                                                        \
    asm volatile("ldmatrix.sync.aligned.m8n8.x4.shared.b16 {%0,%1,%2,%3}, [%4];" \
                 : "=r"((r)[0]), "=r"((r)[1]), "=r"((r)[2]), "=r"((r)[3])     \
                 : "r"(addr))

#define LDSM4T(r, addr)                                                       \
    asm volatile("ldmatrix.sync.aligned.m8n8.x4.trans.shared.b16 {%0,%1,%2,%3}, [%4];" \
                 : "=r"((r)[0]), "=r"((r)[1]), "=r"((r)[2]), "=r"((r)[3])     \
                 : "r"(addr))

#define MMA16816(d, a, b0, b1)                                                \
    asm volatile("mma.sync.aligned.m16n8k16.row.col.f32.f16.f16.f32 "         \
                 "{%0,%1,%2,%3},{%4,%5,%6,%7},{%8,%9},{%0,%1,%2,%3};"         \
                 : "+f"((d)[0]), "+f"((d)[1]), "+f"((d)[2]), "+f"((d)[3])     \
                 : "r"((a)[0]), "r"((a)[1]), "r"((a)[2]), "r"((a)[3]),        \
                   "r"(b0), "r"(b1))

// fp32 -> fp16 plane
__global__ __launch_bounds__(256)
void cvt_hi_k(const float4* __restrict__ src, uint2* __restrict__ h, int n4)
{
    int i = blockIdx.x * 256 + threadIdx.x;
    if (i < n4) {
        float4 v = src[i];
        __half2 h0 = __float22half2_rn(make_float2(v.x, v.y));
        __half2 h1 = __float22half2_rn(make_float2(v.z, v.w));
        h[i] = make_uint2(*(u32*)&h0, *(u32*)&h1);
    }
}

// C[row0:+128, n0:+64] = A[rows,:K] @ W[e,:K,n0:+64], pure fp16 operands.
// EPI=0: fp32 C.  EPI=1: fp16 Ch.
template <int K, int N, int EPI>
__global__ __launch_bounds__(128, 3)
void gemm_moe(const __half* __restrict__ Ah, const __half* __restrict__ Wh,
              const int* __restrict__ bsz, float* __restrict__ C,
              __half* __restrict__ Ch)
{
    extern __shared__ __half sm[];
    const u32 sbase = smem_u32(sm);
    const int tid = threadIdx.x;
    const int lane = tid & 31;
    const int wid = tid >> 5;
    const int warp_m = wid & 1;    // 2 warps along m (64 rows each)
    const int warp_n = wid >> 1;   // 2 warps along n (32 cols each)
    const int row0 = blockIdx.y * 128;
    const int n0 = blockIdx.x * 64;

    int cum = 0, e = 0;
#pragma unroll
    for (int i = 0; i < NE; i++) { if (row0 >= cum) e = i; cum += bsz[i]; }
    const size_t woff = (size_t)e * (size_t)K * (size_t)N;

    // ---- cp.async mapping (128 threads): A 4 chunks, B 2 chunks ----
    const int ar = tid >> 2, ac = tid & 3;   // A: rows ar+{0,32,64,96}, chunk ac of 4
    const int bk = tid >> 3, bc = tid & 7;   // B: rows bk, bk+16, chunk bc of 8
    const __half* pAh = Ah + (size_t)(row0 + ar) * K + ac * 8;
    const __half* pBh = Wh + woff + (size_t)bk * N + n0 + bc * 8;
    const u32 dA = sbase + (u32)((ar * A_ROW + ac * 8) * 2);
    const u32 dB = sbase + (u32)(OFF_BH * 2 + (bk * B_ROW + bc * 8) * 2);

    // ---- ldmatrix lane bases ----
    const int a_r = lane & 15, a_c = (lane >> 4) * 8;
    const u32 aoff = sbase + (u32)(((warp_m * 64 + a_r) * A_ROW + a_c) * 2);
    const int b_k = (lane & 7) + 8 * ((lane >> 3) & 1);
    const int b_n = 8 * (lane >> 4);
    const u32 boff = sbase + (u32)((OFF_BH + b_k * B_ROW + warp_n * 32 + b_n) * 2);

    float acc[4][4][4];
#pragma unroll
    for (int mf = 0; mf < 4; mf++)
#pragma unroll
        for (int nf = 0; nf < 4; nf++)
#pragma unroll
            for (int v = 0; v < 4; v++) acc[mf][nf][v] = 0.0f;

    // double-buffered fragments (per half-stage ki)
    u32 fA[2][16], fB[2][8];

    const int NS = K >> 5;

#define LOAD_STAGE(stoff)                                                     \
    do {                                                                      \
        const u32 _a = dA + (stoff);                                          \
        const u32 _b = dB + (stoff);                                          \
        CP16(_a,                       pAh);                                  \
        CP16(_a + 32 * A_ROW * 2,      pAh + (size_t)32 * K);                 \
        CP16(_a + 64 * A_ROW * 2,      pAh + (size_t)64 * K);                 \
        CP16(_a + 96 * A_ROW * 2,      pAh + (size_t)96 * K);                 \
        CP16(_b,                       pBh);                                  \
        CP16(_b + 16 * B_ROW * 2,      pBh + (size_t)16 * N);                 \
        pAh += 32;                                                            \
        pBh += (size_t)32 * N;                                                \
    } while (0)

#define LDSM_FRAGS(b, stoff, ki)                                              \
    do {                                                                      \
        const u32 _ka = aoff + (stoff) + (ki) * 32;                           \
        const u32 _kb = boff + (stoff) + (ki) * (16 * B_ROW * 2);             \
        LDSM4(&fA[b][0],  _ka);                                               \
        LDSM4(&fA[b][4],  _ka + 16 * A_ROW * 2);                              \
        LDSM4(&fA[b][8],  _ka + 32 * A_ROW * 2);                              \
        LDSM4(&fA[b][12], _ka + 48 * A_ROW * 2);                              \
        LDSM4T(&fB[b][0], _kb);                                               \
        LDSM4T(&fB[b][4], _kb + 16 * 2);                                      \
    } while (0)

#define BURST(b)                                                              \
    do {                                                                      \
        _Pragma("unroll")                                                     \
        for (int mf = 0; mf < 4; mf++)                                        \
            _Pragma("unroll")                                                 \
            for (int nf = 0; nf < 4; nf++)                                    \
                MMA16816(acc[mf][nf], &fA[b][mf * 4], fB[b][nf * 2],          \
                         fB[b][nf * 2 + 1]);                                  \
    } while (0)

    LOAD_STAGE(0);         CP_COMMIT();
    LOAD_STAGE(STAGE_B);   CP_COMMIT();

    int sidx = 0;
    for (int s = 0; s < NS; s++) {
        CP_WAIT1();
        __syncthreads();

        if (s + 2 < NS) {
            int pidx = sidx + 2; if (pidx >= 3) pidx -= 3;
            LOAD_STAGE((u32)(pidx * STAGE_B));
        }
        CP_COMMIT();

        const u32 stb = (u32)(sidx * STAGE_B);
        sidx++; if (sidx >= 3) sidx -= 3;

        LDSM_FRAGS(0, stb, 0);          // ki=0 -> buf0
        LDSM_FRAGS(1, stb, 1);          // ki=1 -> buf1 (issue early; no WAR)
        BURST(0);                       // ki0
        BURST(1);                       // ki1
    }
#undef LOAD_STAGE
#undef LDSM_FRAGS
#undef BURST

    // ---- epilogue ----
#pragma unroll
    for (int mf = 0; mf < 4; mf++)
#pragma unroll
        for (int nf = 0; nf < 4; nf++) {
            int r = row0 + warp_m * 64 + mf * 16 + (lane >> 2);
            int c = n0 + warp_n * 32 + nf * 8 + (lane & 3) * 2;
            if (EPI == 0) {
                *(float2*)(C + (size_t)r * N + c) =
                    make_float2(acc[mf][nf][0], acc[mf][nf][1]);
                *(float2*)(C + (size_t)(r + 8) * N + c) =
                    make_float2(acc[mf][nf][2], acc[mf][nf][3]);
            } else {
                __half2 h0 = __float22half2_rn(make_float2(acc[mf][nf][0], acc[mf][nf][1]));
                __half2 h1 = __float22half2_rn(make_float2(acc[mf][nf][2], acc[mf][nf][3]));
                *(u32*)(Ch + (size_t)r * N + c) = *(u32*)&h0;
                *(u32*)(Ch + (size_t)(r + 8) * N + c) = *(u32*)&h1;
            }
        }
}

extern "C" void kernel_launch(void* const* d_in, const int* in_sizes, int n_in,
                              void* d_out, int out_size)
{
    const float* hiddens = (const float*)d_in[0];
    const int*   bsz     = (const int*)d_in[1];
    const float* w1      = (const float*)d_in[2];
    const float* w2      = (const float*)d_in[3];
    float*       out     = (float*)d_out;

    __half *xh, *w1h, *w2h, *uph;
    cudaGetSymbolAddress((void**)&xh, g_xh);
    cudaGetSymbolAddress((void**)&w1h, g_w1h);
    cudaGetSymbolAddress((void**)&w2h, g_w2h);
    cudaGetSymbolAddress((void**)&uph, g_uph);

    cudaFuncSetAttribute(gemm_moe<1024, 4096, 1>, cudaFuncAttributeMaxDynamicSharedMemorySize, SMEM_BYTES);
    cudaFuncSetAttribute(gemm_moe<4096, 1024, 0>, cudaFuncAttributeMaxDynamicSharedMemorySize, SMEM_BYTES);

    {
        int n4 = (TT * HH) / 4;
        cvt_hi_k<<<(n4 + 255) / 256, 256>>>((const float4*)hiddens, (uint2*)xh, n4);
    }
    {
        int n4 = (NE * HH * II) / 4;
        cvt_hi_k<<<(n4 + 255) / 256, 256>>>((const float4*)w1, (uint2*)w1h, n4);
        cvt_hi_k<<<(n4 + 255) / 256, 256>>>((const float4*)w2, (uint2*)w2h, n4);
    }

    // up = hiddens @ w1[e] : K=1024, N=4096 ; fp16 output
    gemm_moe<1024, 4096, 1><<<dim3(II / 64, TT / 128), 128, SMEM_BYTES>>>(
        xh, w1h, bsz, nullptr, uph);
    // down = up @ w2[e] : K=4096, N=1024 ; fp32 output
    gemm_moe<4096, 1024, 0><<<dim3(HH / 64, TT / 128), 128, SMEM_BYTES>>>(
        uph, w2h, bsz, out, nullptr);
}